// round 2
// baseline (speedup 1.0000x reference)
#include <cuda_runtime.h>
#include <mma.h>
#include <math.h>

using namespace nvcuda;

#define NN 20000
#define EE 320000
#define TE (EE + NN)   // edges + self loops

// ---------------- device scratch (no allocations allowed) ----------------
__device__ float g_h1[NN * 512];      // layer1 linear output [N,4,128]
__device__ float g_out1[NN * 512];    // layer1 aggregated -> gelu'd (in place)
__device__ float g_h2[NN * 256];      // layer2 linear output
__device__ float g_asrc1[NN * 4];
__device__ float g_adst1[NN * 4];
__device__ float g_asrc2[NN];
__device__ float g_adst2[NN];
__device__ float g_den1[NN * 4];
__device__ float g_den2[NN];
__device__ float g_alpha1[TE * 4];    // unnormalized exp weights, CSR order
__device__ float g_alpha2[TE];
__device__ int   g_rowptr[NN + 1];
__device__ int   g_col[TE];           // src node per CSR slot
__device__ int   g_deg[NN];
__device__ int   g_cursor[NN];
__device__ int   g_src[EE];
__device__ int   g_dst[EE];
__device__ int   g_is64;

// ---------------- edge dtype detect + convert ----------------
__global__ void k_detect(const void* ei) {
    // If data really is int64, every 8-byte value is in [0, NN). If it is
    // int32, the high word of an 8-byte read is a random index (rarely 0).
    const unsigned long long* p = (const unsigned long long*)ei;
    int ok64 = 1;
    for (int i = 0; i < 4; i++) if (p[i] >= (unsigned long long)NN) ok64 = 0;
    g_is64 = ok64;
}

__global__ void k_convert(const void* ei, int E) {
    int i = blockIdx.x * 256 + threadIdx.x;
    if (i >= E) return;
    int s, d;
    if (g_is64) {
        const long long* p = (const long long*)ei;
        s = (int)p[i]; d = (int)p[E + i];
    } else {
        const int* p = (const int*)ei;
        s = p[i]; d = p[E + i];
    }
    s = min(max(s, 0), NN - 1);
    d = min(max(d, 0), NN - 1);
    g_src[i] = s; g_dst[i] = d;
}

// ---------------- tf32 wmma GEMM: C[M,N] = A[M,K] @ B[K,N] ----------------
// block tile 64x64, BK=32, 8 warps (4x2), warp tile 16x32.
__global__ void gemm_tf32(const float* __restrict__ A, const float* __restrict__ B,
                          float* __restrict__ C, int M, int K, int N)
{
    __shared__ __align__(128) float As[64 * 40];  // [m][k], ld=40
    __shared__ __align__(128) float Bs[32 * 72];  // [k][n], ld=72
    __shared__ __align__(128) float Cs[64 * 72];  // [m][n], ld=72

    const int tid  = threadIdx.x;
    const int warp = tid >> 5;
    const int wm   = warp >> 1;      // 0..3
    const int wn   = warp & 1;       // 0..1
    const int bm   = blockIdx.y * 64;
    const int bn   = blockIdx.x * 64;

    wmma::fragment<wmma::accumulator, 16, 16, 8, float> c0, c1;
    wmma::fill_fragment(c0, 0.0f);
    wmma::fill_fragment(c1, 0.0f);

    for (int kb = 0; kb < K; kb += 32) {
        __syncthreads();
        // load A tile 64x32: 512 float4 slots
        #pragma unroll
        for (int i = 0; i < 2; i++) {
            int slot = tid + i * 256;
            int r = slot >> 3, c4 = slot & 7;
            int grow = bm + r; if (grow > M - 1) grow = M - 1;
            *(float4*)&As[r * 40 + c4 * 4] =
                *(const float4*)&A[(long long)grow * K + kb + c4 * 4];
        }
        // load B tile 32x64: 512 float4 slots
        #pragma unroll
        for (int i = 0; i < 2; i++) {
            int slot = tid + i * 256;
            int r = slot >> 4, c4 = slot & 15;
            *(float4*)&Bs[r * 72 + c4 * 4] =
                *(const float4*)&B[(long long)(kb + r) * N + bn + c4 * 4];
        }
        __syncthreads();

        #pragma unroll
        for (int ks = 0; ks < 4; ks++) {
            wmma::fragment<wmma::matrix_a, 16, 16, 8, wmma::precision::tf32, wmma::row_major> af;
            wmma::fragment<wmma::matrix_b, 16, 16, 8, wmma::precision::tf32, wmma::row_major> bf0, bf1;
            wmma::load_matrix_sync(af, &As[(wm * 16) * 40 + ks * 8], 40);
            #pragma unroll
            for (int t = 0; t < af.num_elements; t++) af.x[t] = wmma::__float_to_tf32(af.x[t]);
            wmma::load_matrix_sync(bf0, &Bs[(ks * 8) * 72 + wn * 32], 72);
            wmma::load_matrix_sync(bf1, &Bs[(ks * 8) * 72 + wn * 32 + 16], 72);
            #pragma unroll
            for (int t = 0; t < bf0.num_elements; t++) bf0.x[t] = wmma::__float_to_tf32(bf0.x[t]);
            #pragma unroll
            for (int t = 0; t < bf1.num_elements; t++) bf1.x[t] = wmma::__float_to_tf32(bf1.x[t]);
            wmma::mma_sync(c0, af, bf0, c0);
            wmma::mma_sync(c1, af, bf1, c1);
        }
    }

    wmma::store_matrix_sync(&Cs[(wm * 16) * 72 + wn * 32], c0, 72, wmma::mem_row_major);
    wmma::store_matrix_sync(&Cs[(wm * 16) * 72 + wn * 32 + 16], c1, 72, wmma::mem_row_major);
    __syncthreads();

    #pragma unroll
    for (int i = 0; i < 4; i++) {
        int slot = tid + i * 256;
        int r = slot >> 4, c4 = slot & 15;
        int grow = bm + r;
        if (grow < M)
            *(float4*)&C[(long long)grow * N + bn + c4 * 4] = *(float4*)&Cs[r * 72 + c4 * 4];
    }
}

// ---------------- CSR build ----------------
__global__ void k_init_deg() {
    int i = blockIdx.x * 256 + threadIdx.x;
    if (i < NN) g_deg[i] = 1;   // self loop
}

__global__ void k_hist(int E) {
    int e = blockIdx.x * 256 + threadIdx.x;
    if (e < E) atomicAdd(&g_deg[g_dst[e]], 1);
}

__global__ void k_scan() {   // single block, 1024 threads
    __shared__ int sh[1024];
    __shared__ int run;
    if (threadIdx.x == 0) run = 0;
    __syncthreads();
    for (int base = 0; base < NN; base += 1024) {
        int i = base + threadIdx.x;
        int v = (i < NN) ? g_deg[i] : 0;
        sh[threadIdx.x] = v;
        __syncthreads();
        for (int o = 1; o < 1024; o <<= 1) {
            int t = (threadIdx.x >= o) ? sh[threadIdx.x - o] : 0;
            __syncthreads();
            sh[threadIdx.x] += t;
            __syncthreads();
        }
        int excl = sh[threadIdx.x] - v;
        if (i < NN) {
            g_rowptr[i] = run + excl;
            g_cursor[i] = run + excl;
        }
        __syncthreads();
        if (threadIdx.x == 1023) run += sh[1023];
        __syncthreads();
    }
    if (threadIdx.x == 0) g_rowptr[NN] = run;
}

__global__ void k_fill(int E) {
    int i = blockIdx.x * 256 + threadIdx.x;
    if (i < E) {
        int p = atomicAdd(&g_cursor[g_dst[i]], 1);
        g_col[p] = g_src[i];
    } else if (i < E + NN) {
        int n = i - E;
        int p = atomicAdd(&g_cursor[n], 1);
        g_col[p] = n;
    }
}

// ---------------- attention scores ----------------
__global__ void k_att1(const float* __restrict__ asrc, const float* __restrict__ adst) {
    int n = blockIdx.x;
    int w = threadIdx.x >> 5, lane = threadIdx.x & 31;
    int off = w * 128 + lane * 4;
    float4 h  = *(const float4*)&g_h1[n * 512 + off];
    float4 s4 = *(const float4*)&asrc[off];
    float4 d4 = *(const float4*)&adst[off];
    float s = h.x * s4.x + h.y * s4.y + h.z * s4.z + h.w * s4.w;
    float d = h.x * d4.x + h.y * d4.y + h.z * d4.z + h.w * d4.w;
    #pragma unroll
    for (int o = 16; o; o >>= 1) {
        s += __shfl_down_sync(0xffffffffu, s, o);
        d += __shfl_down_sync(0xffffffffu, d, o);
    }
    if (lane == 0) { g_asrc1[n * 4 + w] = s; g_adst1[n * 4 + w] = d; }
}

__global__ void k_att2(const float* __restrict__ asrc, const float* __restrict__ adst) {
    int warp = threadIdx.x >> 5, lane = threadIdx.x & 31;
    int n = blockIdx.x * 8 + warp;
    float s = 0.f, d = 0.f;
    #pragma unroll
    for (int i = 0; i < 2; i++) {
        int off = i * 128 + lane * 4;
        float4 h = *(const float4*)&g_h2[n * 256 + off];
        float4 a = *(const float4*)&asrc[off];
        float4 b = *(const float4*)&adst[off];
        s += h.x * a.x + h.y * a.y + h.z * a.z + h.w * a.w;
        d += h.x * b.x + h.y * b.y + h.z * b.z + h.w * b.w;
    }
    #pragma unroll
    for (int o = 16; o; o >>= 1) {
        s += __shfl_down_sync(0xffffffffu, s, o);
        d += __shfl_down_sync(0xffffffffu, d, o);
    }
    if (lane == 0) { g_asrc2[n] = s; g_adst2[n] = d; }
}

// ---------------- segment softmax (warp per dst node) ----------------
__device__ __forceinline__ float lrelu(float v) { return v > 0.f ? v : 0.2f * v; }

__global__ void k_softmax1() {
    int warp = threadIdx.x >> 5, lane = threadIdx.x & 31;
    int n = blockIdx.x * 8 + warp;
    int s0 = g_rowptr[n], s1 = g_rowptr[n + 1];
    float4 ad = *(const float4*)&g_adst1[n * 4];
    float m0 = -1e30f, m1 = -1e30f, m2 = -1e30f, m3 = -1e30f;
    for (int j = s0 + lane; j < s1; j += 32) {
        float4 as = *(const float4*)&g_asrc1[g_col[j] * 4];
        m0 = fmaxf(m0, lrelu(as.x + ad.x));
        m1 = fmaxf(m1, lrelu(as.y + ad.y));
        m2 = fmaxf(m2, lrelu(as.z + ad.z));
        m3 = fmaxf(m3, lrelu(as.w + ad.w));
    }
    #pragma unroll
    for (int o = 16; o; o >>= 1) {
        m0 = fmaxf(m0, __shfl_xor_sync(0xffffffffu, m0, o));
        m1 = fmaxf(m1, __shfl_xor_sync(0xffffffffu, m1, o));
        m2 = fmaxf(m2, __shfl_xor_sync(0xffffffffu, m2, o));
        m3 = fmaxf(m3, __shfl_xor_sync(0xffffffffu, m3, o));
    }
    float t0 = 0.f, t1 = 0.f, t2 = 0.f, t3 = 0.f;
    for (int j = s0 + lane; j < s1; j += 32) {
        float4 as = *(const float4*)&g_asrc1[g_col[j] * 4];
        float4 p;
        p.x = __expf(lrelu(as.x + ad.x) - m0); t0 += p.x;
        p.y = __expf(lrelu(as.y + ad.y) - m1); t1 += p.y;
        p.z = __expf(lrelu(as.z + ad.z) - m2); t2 += p.z;
        p.w = __expf(lrelu(as.w + ad.w) - m3); t3 += p.w;
        *(float4*)&g_alpha1[j * 4] = p;
    }
    #pragma unroll
    for (int o = 16; o; o >>= 1) {
        t0 += __shfl_xor_sync(0xffffffffu, t0, o);
        t1 += __shfl_xor_sync(0xffffffffu, t1, o);
        t2 += __shfl_xor_sync(0xffffffffu, t2, o);
        t3 += __shfl_xor_sync(0xffffffffu, t3, o);
    }
    if (lane == 0) {
        float4 t = make_float4(t0, t1, t2, t3);
        *(float4*)&g_den1[n * 4] = t;
    }
}

__global__ void k_softmax2() {
    int warp = threadIdx.x >> 5, lane = threadIdx.x & 31;
    int n = blockIdx.x * 8 + warp;
    int s0 = g_rowptr[n], s1 = g_rowptr[n + 1];
    float ad = g_adst2[n];
    float m = -1e30f;
    for (int j = s0 + lane; j < s1; j += 32)
        m = fmaxf(m, lrelu(g_asrc2[g_col[j]] + ad));
    #pragma unroll
    for (int o = 16; o; o >>= 1) m = fmaxf(m, __shfl_xor_sync(0xffffffffu, m, o));
    float t = 0.f;
    for (int j = s0 + lane; j < s1; j += 32) {
        float p = __expf(lrelu(g_asrc2[g_col[j]] + ad) - m);
        t += p;
        g_alpha2[j] = p;
    }
    #pragma unroll
    for (int o = 16; o; o >>= 1) t += __shfl_xor_sync(0xffffffffu, t, o);
    if (lane == 0) g_den2[n] = t;
}

// ---------------- CSR aggregation (atomic-free) ----------------
__global__ void k_aggregate1() {
    int wid = blockIdx.x * 8 + (threadIdx.x >> 5);
    int n = wid >> 2, h = wid & 3, lane = threadIdx.x & 31;
    int s0 = g_rowptr[n], s1 = g_rowptr[n + 1];
    int off = h * 128 + lane * 4;
    float4 acc = make_float4(0.f, 0.f, 0.f, 0.f);
    int j = s0;
    for (; j + 1 < s1; j += 2) {
        int c0 = g_col[j], c1 = g_col[j + 1];
        float a0 = g_alpha1[j * 4 + h];
        float a1 = g_alpha1[(j + 1) * 4 + h];
        float4 v0 = *(const float4*)&g_h1[c0 * 512 + off];
        float4 v1 = *(const float4*)&g_h1[c1 * 512 + off];
        acc.x += a0 * v0.x + a1 * v1.x;
        acc.y += a0 * v0.y + a1 * v1.y;
        acc.z += a0 * v0.z + a1 * v1.z;
        acc.w += a0 * v0.w + a1 * v1.w;
    }
    if (j < s1) {
        int c0 = g_col[j];
        float a0 = g_alpha1[j * 4 + h];
        float4 v0 = *(const float4*)&g_h1[c0 * 512 + off];
        acc.x += a0 * v0.x; acc.y += a0 * v0.y;
        acc.z += a0 * v0.z; acc.w += a0 * v0.w;
    }
    float inv = 1.0f / g_den1[n * 4 + h];
    acc.x *= inv; acc.y *= inv; acc.z *= inv; acc.w *= inv;
    *(float4*)&g_out1[n * 512 + off] = acc;
}

__global__ void k_aggregate2(const float* __restrict__ b2, float* __restrict__ out) {
    int wid = blockIdx.x * 8 + (threadIdx.x >> 5);
    int n = wid, lane = threadIdx.x & 31;
    int s0 = g_rowptr[n], s1 = g_rowptr[n + 1];
    float4 acc0 = make_float4(0.f, 0.f, 0.f, 0.f);
    float4 acc1 = make_float4(0.f, 0.f, 0.f, 0.f);
    for (int j = s0; j < s1; j++) {
        int c = g_col[j];
        float a = g_alpha2[j];
        float4 v0 = *(const float4*)&g_h2[c * 256 + lane * 4];
        float4 v1 = *(const float4*)&g_h2[c * 256 + 128 + lane * 4];
        acc0.x += a * v0.x; acc0.y += a * v0.y; acc0.z += a * v0.z; acc0.w += a * v0.w;
        acc1.x += a * v1.x; acc1.y += a * v1.y; acc1.z += a * v1.z; acc1.w += a * v1.w;
    }
    float inv = 1.0f / g_den2[n];
    float4 bb0 = *(const float4*)&b2[lane * 4];
    float4 bb1 = *(const float4*)&b2[128 + lane * 4];
    float4 o0, o1;
    o0.x = acc0.x * inv + bb0.x; o0.y = acc0.y * inv + bb0.y;
    o0.z = acc0.z * inv + bb0.z; o0.w = acc0.w * inv + bb0.w;
    o1.x = acc1.x * inv + bb1.x; o1.y = acc1.y * inv + bb1.y;
    o1.z = acc1.z * inv + bb1.z; o1.w = acc1.w * inv + bb1.w;
    *(float4*)&out[n * 256 + lane * 4] = o0;
    *(float4*)&out[n * 256 + 128 + lane * 4] = o1;
}

// ---------------- bias + exact GELU (in place on g_out1) ----------------
__global__ void k_gelu(const float* __restrict__ b1) {
    int i = blockIdx.x * 256 + threadIdx.x;
    if (i >= NN * 512) return;
    float y = g_out1[i] + b1[i & 511];
    g_out1[i] = 0.5f * y * (1.0f + erff(y * 0.70710678118654752f));
}

// ---------------- host launcher ----------------
extern "C" void kernel_launch(void* const* d_in, const int* in_sizes, int n_in,
                              void* d_out, int out_size)
{
    const float* x   = (const float*)d_in[0];
    const void*  ei  = d_in[1];
    const float* W1  = (const float*)d_in[2];
    const float* as1 = (const float*)d_in[3];
    const float* ad1 = (const float*)d_in[4];
    const float* b1  = (const float*)d_in[5];
    const float* W2  = (const float*)d_in[6];
    const float* as2 = (const float*)d_in[7];
    const float* ad2 = (const float*)d_in[8];
    const float* b2  = (const float*)d_in[9];
    float*       out = (float*)d_out;
    const int E = in_sizes[1] / 2;   // 320000

    float *p_h1, *p_out1, *p_h2;
    cudaGetSymbolAddress((void**)&p_h1,   g_h1);
    cudaGetSymbolAddress((void**)&p_out1, g_out1);
    cudaGetSymbolAddress((void**)&p_h2,   g_h2);

    // edge dtype detect + convert, then CSR build
    k_detect<<<1, 1>>>(ei);
    k_convert<<<(E + 255) / 256, 256>>>(ei, E);
    k_init_deg<<<(NN + 255) / 256, 256>>>();
    k_hist<<<(E + 255) / 256, 256>>>(E);
    k_scan<<<1, 1024>>>();
    k_fill<<<(E + NN + 255) / 256, 256>>>(E);

    // layer 1
    gemm_tf32<<<dim3(512 / 64, (NN + 63) / 64), 256>>>(x, W1, p_h1, NN, 256, 512);
    k_att1<<<NN, 128>>>(as1, ad1);
    k_softmax1<<<NN / 8, 256>>>();
    k_aggregate1<<<(NN * 4) / 8, 256>>>();
    k_gelu<<<(NN * 512 + 255) / 256, 256>>>(b1);

    // layer 2
    gemm_tf32<<<dim3(256 / 64, (NN + 63) / 64), 256>>>(p_out1, W2, p_h2, NN, 512, 256);
    k_att2<<<NN / 8, 256>>>(as2, ad2);
    k_softmax2<<<NN / 8, 256>>>();
    k_aggregate2<<<NN / 8, 256>>>(b2, out);
}

// round 3
// speedup vs baseline: 1.0106x; 1.0106x over previous
#include <cuda_runtime.h>
#include <cuda_pipeline.h>
#include <mma.h>
#include <math.h>

using namespace nvcuda;

#define NN 20000
#define EE 320000
#define TE (EE + NN)   // edges + self loops

// ---------------- device scratch (no allocations allowed) ----------------
__device__ float g_h1[NN * 512];      // layer1 linear output [N,4,128]
__device__ float g_out1[NN * 512];    // layer1 aggregated + bias + gelu
__device__ float g_h2[NN * 256];      // layer2 linear output
__device__ float g_asrc1[NN * 4];
__device__ float g_adst1[NN * 4];
__device__ float g_asrc2[NN];
__device__ float g_adst2[NN];
__device__ float g_den1[NN * 4];
__device__ float g_den2[NN];
__device__ float g_alpha1[TE * 4];    // unnormalized exp weights, CSR order
__device__ float g_alpha2[TE];
__device__ int   g_rowptr[NN + 1];
__device__ int   g_col[TE];           // src node per CSR slot
__device__ int   g_deg[NN];
__device__ int   g_cursor[NN];
__device__ int   g_src[EE];
__device__ int   g_dst[EE];
__device__ int   g_is64;

// ---------------- edge dtype detect + convert ----------------
__global__ void k_detect(const void* ei) {
    const unsigned long long* p = (const unsigned long long*)ei;
    int ok64 = 1;
    for (int i = 0; i < 4; i++) if (p[i] >= (unsigned long long)NN) ok64 = 0;
    g_is64 = ok64;
}

__global__ void k_convert(const void* ei, int E) {
    int i = blockIdx.x * 256 + threadIdx.x;
    if (i >= E) return;
    int s, d;
    if (g_is64) {
        const long long* p = (const long long*)ei;
        s = (int)p[i]; d = (int)p[E + i];
    } else {
        const int* p = (const int*)ei;
        s = p[i]; d = p[E + i];
    }
    s = min(max(s, 0), NN - 1);
    d = min(max(d, 0), NN - 1);
    g_src[i] = s; g_dst[i] = d;
}

// ---------------- tf32 GEMM, 128x128x32, cp.async double buffered ----------
// 8 warps as 2(m) x 4(n); warp tile 64x32 = 4x2 wmma 16x16x8 fragments.
#define BM 128
#define BN 128
#define BK 32
#define LDA 36      // 128x32 A tile, padded
#define LDB 132     // 32x128 B tile, padded
#define LDC 132
#define A_TILE (BM * LDA)      // 4608 floats
#define B_TILE (BK * LDB)      // 4224 floats
#define GEMM_SMEM ((2 * A_TILE + 2 * B_TILE) * 4)   // 70656 bytes

__device__ __forceinline__ void gemm_load_stage(
    float* As, float* Bs, const float* A, const float* B,
    int M, int K, int N, int bm, int bn, int kb, int tid)
{
    // A: 128x32 -> 1024 float4 slots
    #pragma unroll
    for (int i = 0; i < 4; i++) {
        int slot = i * 256 + tid;
        int r = slot >> 3, c4 = slot & 7;
        int grow = bm + r; if (grow > M - 1) grow = M - 1;
        __pipeline_memcpy_async(&As[r * LDA + c4 * 4],
                                &A[(long long)grow * K + kb + c4 * 4], 16);
    }
    // B: 32x128 -> 1024 float4 slots
    #pragma unroll
    for (int i = 0; i < 4; i++) {
        int slot = i * 256 + tid;
        int r = slot >> 5, c4 = slot & 31;
        __pipeline_memcpy_async(&Bs[r * LDB + c4 * 4],
                                &B[(long long)(kb + r) * N + bn + c4 * 4], 16);
    }
}

__global__ void gemm_tf32(const float* __restrict__ A, const float* __restrict__ B,
                          float* __restrict__ C, int M, int K, int N)
{
    extern __shared__ float smem[];
    float* As[2] = { smem, smem + A_TILE };
    float* Bs[2] = { smem + 2 * A_TILE, smem + 2 * A_TILE + B_TILE };
    float* Cs = smem;   // reused for epilogue (16896 <= 17664 floats)

    const int tid  = threadIdx.x;
    const int warp = tid >> 5;
    const int wm   = warp >> 2;      // 0..1
    const int wn   = warp & 3;       // 0..3
    const int bm   = blockIdx.y * BM;
    const int bn   = blockIdx.x * BN;

    wmma::fragment<wmma::accumulator, 16, 16, 8, float> acc[4][2];
    #pragma unroll
    for (int i = 0; i < 4; i++)
        #pragma unroll
        for (int j = 0; j < 2; j++)
            wmma::fill_fragment(acc[i][j], 0.0f);

    const int T = K / BK;
    gemm_load_stage(As[0], Bs[0], A, B, M, K, N, bm, bn, 0, tid);
    __pipeline_commit();

    for (int t = 0; t < T; t++) {
        if (t + 1 < T) {
            gemm_load_stage(As[(t + 1) & 1], Bs[(t + 1) & 1], A, B, M, K, N,
                            bm, bn, (t + 1) * BK, tid);
            __pipeline_commit();
            __pipeline_wait_prior(1);
        } else {
            __pipeline_wait_prior(0);
        }
        __syncthreads();

        const float* at = As[t & 1];
        const float* bt = Bs[t & 1];
        #pragma unroll
        for (int ks = 0; ks < 4; ks++) {
            wmma::fragment<wmma::matrix_a, 16, 16, 8, wmma::precision::tf32, wmma::row_major> af[4];
            wmma::fragment<wmma::matrix_b, 16, 16, 8, wmma::precision::tf32, wmma::row_major> bf[2];
            #pragma unroll
            for (int i = 0; i < 4; i++) {
                wmma::load_matrix_sync(af[i], &at[(wm * 64 + i * 16) * LDA + ks * 8], LDA);
                #pragma unroll
                for (int e = 0; e < af[i].num_elements; e++)
                    af[i].x[e] = wmma::__float_to_tf32(af[i].x[e]);
            }
            #pragma unroll
            for (int j = 0; j < 2; j++) {
                wmma::load_matrix_sync(bf[j], &bt[(ks * 8) * LDB + wn * 32 + j * 16], LDB);
                #pragma unroll
                for (int e = 0; e < bf[j].num_elements; e++)
                    bf[j].x[e] = wmma::__float_to_tf32(bf[j].x[e]);
            }
            #pragma unroll
            for (int i = 0; i < 4; i++)
                #pragma unroll
                for (int j = 0; j < 2; j++)
                    wmma::mma_sync(acc[i][j], af[i], bf[j], acc[i][j]);
        }
        __syncthreads();
    }

    // epilogue: stage through smem for float4 stores
    #pragma unroll
    for (int i = 0; i < 4; i++)
        #pragma unroll
        for (int j = 0; j < 2; j++)
            wmma::store_matrix_sync(&Cs[(wm * 64 + i * 16) * LDC + wn * 32 + j * 16],
                                    acc[i][j], LDC, wmma::mem_row_major);
    __syncthreads();

    #pragma unroll
    for (int i = 0; i < 16; i++) {
        int slot = i * 256 + tid;
        int r = slot >> 5, c4 = slot & 31;
        int grow = bm + r;
        if (grow < M)
            *(float4*)&C[(long long)grow * N + bn + c4 * 4] = *(float4*)&Cs[r * LDC + c4 * 4];
    }
}

// ---------------- CSR build ----------------
__global__ void k_init_deg() {
    int i = blockIdx.x * 256 + threadIdx.x;
    if (i < NN) g_deg[i] = 1;   // self loop
}

__global__ void k_hist(int E) {
    int e = blockIdx.x * 256 + threadIdx.x;
    if (e < E) atomicAdd(&g_deg[g_dst[e]], 1);
}

__global__ void k_scan() {   // single block, 1024 threads
    __shared__ int sh[1024];
    __shared__ int run;
    if (threadIdx.x == 0) run = 0;
    __syncthreads();
    for (int base = 0; base < NN; base += 1024) {
        int i = base + threadIdx.x;
        int v = (i < NN) ? g_deg[i] : 0;
        sh[threadIdx.x] = v;
        __syncthreads();
        for (int o = 1; o < 1024; o <<= 1) {
            int t = (threadIdx.x >= o) ? sh[threadIdx.x - o] : 0;
            __syncthreads();
            sh[threadIdx.x] += t;
            __syncthreads();
        }
        int excl = sh[threadIdx.x] - v;
        if (i < NN) {
            g_rowptr[i] = run + excl;
            g_cursor[i] = run + excl;
        }
        __syncthreads();
        if (threadIdx.x == 1023) run += sh[1023];
        __syncthreads();
    }
    if (threadIdx.x == 0) g_rowptr[NN] = run;
}

__global__ void k_fill(int E) {
    int i = blockIdx.x * 256 + threadIdx.x;
    if (i < E) {
        int p = atomicAdd(&g_cursor[g_dst[i]], 1);
        g_col[p] = g_src[i];
    } else if (i < E + NN) {
        int n = i - E;
        int p = atomicAdd(&g_cursor[n], 1);
        g_col[p] = n;
    }
}

// ---------------- attention scores ----------------
__global__ void k_att1(const float* __restrict__ asrc, const float* __restrict__ adst) {
    int n = blockIdx.x;
    int w = threadIdx.x >> 5, lane = threadIdx.x & 31;
    int off = w * 128 + lane * 4;
    float4 h  = *(const float4*)&g_h1[n * 512 + off];
    float4 s4 = *(const float4*)&asrc[off];
    float4 d4 = *(const float4*)&adst[off];
    float s = h.x * s4.x + h.y * s4.y + h.z * s4.z + h.w * s4.w;
    float d = h.x * d4.x + h.y * d4.y + h.z * d4.z + h.w * d4.w;
    #pragma unroll
    for (int o = 16; o; o >>= 1) {
        s += __shfl_down_sync(0xffffffffu, s, o);
        d += __shfl_down_sync(0xffffffffu, d, o);
    }
    if (lane == 0) { g_asrc1[n * 4 + w] = s; g_adst1[n * 4 + w] = d; }
}

__global__ void k_att2(const float* __restrict__ asrc, const float* __restrict__ adst) {
    int warp = threadIdx.x >> 5, lane = threadIdx.x & 31;
    int n = blockIdx.x * 8 + warp;
    float s = 0.f, d = 0.f;
    #pragma unroll
    for (int i = 0; i < 2; i++) {
        int off = i * 128 + lane * 4;
        float4 h = *(const float4*)&g_h2[n * 256 + off];
        float4 a = *(const float4*)&asrc[off];
        float4 b = *(const float4*)&adst[off];
        s += h.x * a.x + h.y * a.y + h.z * a.z + h.w * a.w;
        d += h.x * b.x + h.y * b.y + h.z * b.z + h.w * b.w;
    }
    #pragma unroll
    for (int o = 16; o; o >>= 1) {
        s += __shfl_down_sync(0xffffffffu, s, o);
        d += __shfl_down_sync(0xffffffffu, d, o);
    }
    if (lane == 0) { g_asrc2[n] = s; g_adst2[n] = d; }
}

// ---------------- segment softmax (warp per dst node) ----------------
__device__ __forceinline__ float lrelu(float v) { return v > 0.f ? v : 0.2f * v; }

__global__ void k_softmax1() {
    int warp = threadIdx.x >> 5, lane = threadIdx.x & 31;
    int n = blockIdx.x * 8 + warp;
    int s0 = g_rowptr[n], s1 = g_rowptr[n + 1];
    float4 ad = *(const float4*)&g_adst1[n * 4];
    float m0 = -1e30f, m1 = -1e30f, m2 = -1e30f, m3 = -1e30f;
    for (int j = s0 + lane; j < s1; j += 32) {
        float4 as = *(const float4*)&g_asrc1[g_col[j] * 4];
        m0 = fmaxf(m0, lrelu(as.x + ad.x));
        m1 = fmaxf(m1, lrelu(as.y + ad.y));
        m2 = fmaxf(m2, lrelu(as.z + ad.z));
        m3 = fmaxf(m3, lrelu(as.w + ad.w));
    }
    #pragma unroll
    for (int o = 16; o; o >>= 1) {
        m0 = fmaxf(m0, __shfl_xor_sync(0xffffffffu, m0, o));
        m1 = fmaxf(m1, __shfl_xor_sync(0xffffffffu, m1, o));
        m2 = fmaxf(m2, __shfl_xor_sync(0xffffffffu, m2, o));
        m3 = fmaxf(m3, __shfl_xor_sync(0xffffffffu, m3, o));
    }
    float t0 = 0.f, t1 = 0.f, t2 = 0.f, t3 = 0.f;
    for (int j = s0 + lane; j < s1; j += 32) {
        float4 as = *(const float4*)&g_asrc1[g_col[j] * 4];
        float4 p;
        p.x = __expf(lrelu(as.x + ad.x) - m0); t0 += p.x;
        p.y = __expf(lrelu(as.y + ad.y) - m1); t1 += p.y;
        p.z = __expf(lrelu(as.z + ad.z) - m2); t2 += p.z;
        p.w = __expf(lrelu(as.w + ad.w) - m3); t3 += p.w;
        *(float4*)&g_alpha1[j * 4] = p;
    }
    #pragma unroll
    for (int o = 16; o; o >>= 1) {
        t0 += __shfl_xor_sync(0xffffffffu, t0, o);
        t1 += __shfl_xor_sync(0xffffffffu, t1, o);
        t2 += __shfl_xor_sync(0xffffffffu, t2, o);
        t3 += __shfl_xor_sync(0xffffffffu, t3, o);
    }
    if (lane == 0) {
        float4 t = make_float4(t0, t1, t2, t3);
        *(float4*)&g_den1[n * 4] = t;
    }
}

__global__ void k_softmax2() {
    int warp = threadIdx.x >> 5, lane = threadIdx.x & 31;
    int n = blockIdx.x * 8 + warp;
    int s0 = g_rowptr[n], s1 = g_rowptr[n + 1];
    float ad = g_adst2[n];
    float m = -1e30f;
    for (int j = s0 + lane; j < s1; j += 32)
        m = fmaxf(m, lrelu(g_asrc2[g_col[j]] + ad));
    #pragma unroll
    for (int o = 16; o; o >>= 1) m = fmaxf(m, __shfl_xor_sync(0xffffffffu, m, o));
    float t = 0.f;
    for (int j = s0 + lane; j < s1; j += 32) {
        float p = __expf(lrelu(g_asrc2[g_col[j]] + ad) - m);
        t += p;
        g_alpha2[j] = p;
    }
    #pragma unroll
    for (int o = 16; o; o >>= 1) t += __shfl_xor_sync(0xffffffffu, t, o);
    if (lane == 0) g_den2[n] = t;
}

// ------------- CSR aggregation layer 1: + bias + exact GELU fused ---------
__global__ void k_aggregate1(const float* __restrict__ b1) {
    int wid = blockIdx.x * 8 + (threadIdx.x >> 5);
    int n = wid >> 2, h = wid & 3, lane = threadIdx.x & 31;
    int s0 = g_rowptr[n], s1 = g_rowptr[n + 1];
    int off = h * 128 + lane * 4;
    const float* hb = g_h1 + off;
    float4 acc0 = make_float4(0.f, 0.f, 0.f, 0.f);
    float4 acc1 = make_float4(0.f, 0.f, 0.f, 0.f);
    int j = s0;
    for (; j + 3 < s1; j += 4) {
        int c0 = g_col[j],     c1 = g_col[j + 1];
        int c2 = g_col[j + 2], c3 = g_col[j + 3];
        float a0 = g_alpha1[j * 4 + h],       a1 = g_alpha1[(j + 1) * 4 + h];
        float a2 = g_alpha1[(j + 2) * 4 + h], a3 = g_alpha1[(j + 3) * 4 + h];
        float4 v0 = *(const float4*)&hb[c0 * 512];
        float4 v1 = *(const float4*)&hb[c1 * 512];
        float4 v2 = *(const float4*)&hb[c2 * 512];
        float4 v3 = *(const float4*)&hb[c3 * 512];
        acc0.x += a0 * v0.x + a2 * v2.x;  acc1.x += a1 * v1.x + a3 * v3.x;
        acc0.y += a0 * v0.y + a2 * v2.y;  acc1.y += a1 * v1.y + a3 * v3.y;
        acc0.z += a0 * v0.z + a2 * v2.z;  acc1.z += a1 * v1.z + a3 * v3.z;
        acc0.w += a0 * v0.w + a2 * v2.w;  acc1.w += a1 * v1.w + a3 * v3.w;
    }
    for (; j < s1; j++) {
        int c0 = g_col[j];
        float a0 = g_alpha1[j * 4 + h];
        float4 v0 = *(const float4*)&hb[c0 * 512];
        acc0.x += a0 * v0.x; acc0.y += a0 * v0.y;
        acc0.z += a0 * v0.z; acc0.w += a0 * v0.w;
    }
    float inv = 1.0f / g_den1[n * 4 + h];
    float4 bb = *(const float4*)&b1[off];
    float4 y;
    y.x = (acc0.x + acc1.x) * inv + bb.x;
    y.y = (acc0.y + acc1.y) * inv + bb.y;
    y.z = (acc0.z + acc1.z) * inv + bb.z;
    y.w = (acc0.w + acc1.w) * inv + bb.w;
    // exact GELU: y * Phi(y)
    y.x = y.x * normcdff(y.x);
    y.y = y.y * normcdff(y.y);
    y.z = y.z * normcdff(y.z);
    y.w = y.w * normcdff(y.w);
    *(float4*)&g_out1[n * 512 + off] = y;
}

__global__ void k_aggregate2(const float* __restrict__ b2, float* __restrict__ out) {
    int wid = blockIdx.x * 8 + (threadIdx.x >> 5);
    int n = wid, lane = threadIdx.x & 31;
    int s0 = g_rowptr[n], s1 = g_rowptr[n + 1];
    float4 acc0 = make_float4(0.f, 0.f, 0.f, 0.f);
    float4 acc1 = make_float4(0.f, 0.f, 0.f, 0.f);
    float4 acc2 = make_float4(0.f, 0.f, 0.f, 0.f);
    float4 acc3 = make_float4(0.f, 0.f, 0.f, 0.f);
    const float* hb = g_h2 + lane * 4;
    int j = s0;
    for (; j + 1 < s1; j += 2) {
        int c0 = g_col[j], c1 = g_col[j + 1];
        float a0 = g_alpha2[j], a1 = g_alpha2[j + 1];
        float4 u0 = *(const float4*)&hb[c0 * 256];
        float4 u1 = *(const float4*)&hb[c0 * 256 + 128];
        float4 w0 = *(const float4*)&hb[c1 * 256];
        float4 w1 = *(const float4*)&hb[c1 * 256 + 128];
        acc0.x += a0 * u0.x; acc0.y += a0 * u0.y; acc0.z += a0 * u0.z; acc0.w += a0 * u0.w;
        acc1.x += a0 * u1.x; acc1.y += a0 * u1.y; acc1.z += a0 * u1.z; acc1.w += a0 * u1.w;
        acc2.x += a1 * w0.x; acc2.y += a1 * w0.y; acc2.z += a1 * w0.z; acc2.w += a1 * w0.w;
        acc3.x += a1 * w1.x; acc3.y += a1 * w1.y; acc3.z += a1 * w1.z; acc3.w += a1 * w1.w;
    }
    if (j < s1) {
        int c0 = g_col[j];
        float a0 = g_alpha2[j];
        float4 u0 = *(const float4*)&hb[c0 * 256];
        float4 u1 = *(const float4*)&hb[c0 * 256 + 128];
        acc0.x += a0 * u0.x; acc0.y += a0 * u0.y; acc0.z += a0 * u0.z; acc0.w += a0 * u0.w;
        acc1.x += a0 * u1.x; acc1.y += a0 * u1.y; acc1.z += a0 * u1.z; acc1.w += a0 * u1.w;
    }
    float inv = 1.0f / g_den2[n];
    float4 bb0 = *(const float4*)&b2[lane * 4];
    float4 bb1 = *(const float4*)&b2[128 + lane * 4];
    float4 o0, o1;
    o0.x = (acc0.x + acc2.x) * inv + bb0.x; o0.y = (acc0.y + acc2.y) * inv + bb0.y;
    o0.z = (acc0.z + acc2.z) * inv + bb0.z; o0.w = (acc0.w + acc2.w) * inv + bb0.w;
    o1.x = (acc1.x + acc3.x) * inv + bb1.x; o1.y = (acc1.y + acc3.y) * inv + bb1.y;
    o1.z = (acc1.z + acc3.z) * inv + bb1.z; o1.w = (acc1.w + acc3.w) * inv + bb1.w;
    *(float4*)&out[n * 256 + lane * 4] = o0;
    *(float4*)&out[n * 256 + 128 + lane * 4] = o1;
}

// ---------------- host launcher ----------------
extern "C" void kernel_launch(void* const* d_in, const int* in_sizes, int n_in,
                              void* d_out, int out_size)
{
    const float* x   = (const float*)d_in[0];
    const void*  ei  = d_in[1];
    const float* W1  = (const float*)d_in[2];
    const float* as1 = (const float*)d_in[3];
    const float* ad1 = (const float*)d_in[4];
    const float* b1  = (const float*)d_in[5];
    const float* W2  = (const float*)d_in[6];
    const float* as2 = (const float*)d_in[7];
    const float* ad2 = (const float*)d_in[8];
    const float* b2  = (const float*)d_in[9];
    float*       out = (float*)d_out;
    const int E = in_sizes[1] / 2;   // 320000

    float *p_h1, *p_out1, *p_h2;
    cudaGetSymbolAddress((void**)&p_h1,   g_h1);
    cudaGetSymbolAddress((void**)&p_out1, g_out1);
    cudaGetSymbolAddress((void**)&p_h2,   g_h2);

    cudaFuncSetAttribute(gemm_tf32, cudaFuncAttributeMaxDynamicSharedMemorySize, GEMM_SMEM);

    // edge dtype detect + convert, then CSR build
    k_detect<<<1, 1>>>(ei);
    k_convert<<<(E + 255) / 256, 256>>>(ei, E);
    k_init_deg<<<(NN + 255) / 256, 256>>>();
    k_hist<<<(E + 255) / 256, 256>>>(E);
    k_scan<<<1, 1024>>>();
    k_fill<<<(E + NN + 255) / 256, 256>>>(E);

    // layer 1
    gemm_tf32<<<dim3(512 / BN, (NN + BM - 1) / BM), 256, GEMM_SMEM>>>(x, W1, p_h1, NN, 256, 512);
    k_att1<<<NN, 128>>>(as1, ad1);
    k_softmax1<<<NN / 8, 256>>>();
    k_aggregate1<<<(NN * 4) / 8, 256>>>(b1);

    // layer 2
    gemm_tf32<<<dim3(256 / BN, (NN + BM - 1) / BM), 256, GEMM_SMEM>>>(p_out1, W2, p_h2, NN, 512, 256);
    k_att2<<<NN / 8, 256>>>(as2, ad2);
    k_softmax2<<<NN / 8, 256>>>();
    k_aggregate2<<<NN / 8, 256>>>(b2, out);
}